// round 13
// baseline (speedup 1.0000x reference)
#include <cuda_runtime.h>

// PyramidROIAlign: B=2, N=1000 boxes, C=256, 7x7 pool. Single fused kernel.
// R12 champion (128-thread CTA = 8 items, guarded param phase -> barrier ->
// 16-lanes/item unroll-4 gather, regs pinned to 32, __stcs stores) plus
// max-L1 shared-memory carveout (kernel uses only 320B SMEM; give the rest
// to L1D so corner-row reuse hits L1 instead of paying ~234cyc L2 trips).

#define POOL 7
#define NPTS (POOL * POOL)
#define CCH 256
#define LANES 16
#define ITEMS_PER_CTA 8
#define CTA_THREADS 128

__global__ void __launch_bounds__(CTA_THREADS, 16)
roi_fused_kernel(const float* __restrict__ boxes,
                 const float* __restrict__ image_shape,
                 const float* __restrict__ P2,
                 const float* __restrict__ P3,
                 const float* __restrict__ P4,
                 const float* __restrict__ P5,
                 float* __restrict__ out,
                 int total_items, int boxes_per_batch)
{
    __shared__ ulonglong4 s_addr[ITEMS_PER_CTA];
    __shared__ float2     s_w[ITEMS_PER_CTA];

    const int item_base = blockIdx.x * ITEMS_PER_CTA;
    const int tid = threadIdx.x;

    if (tid < ITEMS_PER_CTA) {
        const int item = item_base + tid;
        if (item < total_items) {
            const int bn = item / NPTS;
            const int pt = item - bn * NPTS;
            const int py = pt / POOL;
            const int px = pt - py * POOL;
            const int b  = bn / boxes_per_batch;

            const float4 bx = ((const float4*)boxes)[bn];
            const float y1 = bx.x, x1 = bx.y, y2 = bx.z, x2 = bx.w;
            const float h = y2 - y1;
            const float w = x2 - x1;

            // Level selection — exact reference fp32 op order; rintf == jnp.round.
            const float area = image_shape[0] * image_shape[1];
            float lvlf = log2f(sqrtf(h * w) / (224.0f / sqrtf(area)));
            lvlf = fminf(5.0f, fmaxf(2.0f, 4.0f + rintf(lvlf)));
            const int lvl = (int)lvlf;

            const float* fmap;
            int H;
            if (lvl == 2)      { fmap = P2; H = 256; }
            else if (lvl == 3) { fmap = P3; H = 128; }
            else if (lvl == 4) { fmap = P4; H = 64;  }
            else               { fmap = P5; H = 32;  }
            const int W = H;

            // Reference order: in_y = (y1 + h*gy) * (H-1)
            const float gy = (float)py * (1.0f / 6.0f);
            const float gx = (float)px * (1.0f / 6.0f);
            const float in_y = (y1 + h * gy) * (float)(H - 1);
            const float in_x = (x1 + w * gx) * (float)(W - 1);

            const float y0f = floorf(in_y);
            const float x0f = floorf(in_x);
            const float wy = in_y - y0f;
            const float wx = in_x - x0f;

            int y0  = min(max((int)y0f, 0), H - 1);
            int y1i = min(y0 + 1, H - 1);
            int x0  = min(max((int)x0f, 0), W - 1);
            int x1i = min(x0 + 1, W - 1);

            const unsigned long long base =
                (unsigned long long)fmap + (unsigned long long)b * H * W * CCH * 4ull;
            const unsigned long long rowT = base + (unsigned long long)(y0  * W) * (CCH * 4ull);
            const unsigned long long rowB = base + (unsigned long long)(y1i * W) * (CCH * 4ull);

            ulonglong4 a;
            a.x = rowT + (unsigned long long)x0  * (CCH * 4ull);
            a.y = rowT + (unsigned long long)x1i * (CCH * 4ull);
            a.z = rowB + (unsigned long long)x0  * (CCH * 4ull);
            a.w = rowB + (unsigned long long)x1i * (CCH * 4ull);
            s_addr[tid] = a;
            s_w[tid] = make_float2(wx, wy);
        }
    }
    __syncthreads();

    const int local = tid >> 4;            // item within CTA (0..7)
    const int lane  = tid & (LANES - 1);   // float4 lane group
    const int item = item_base + local;
    if (item >= total_items) return;

    const ulonglong4 a = s_addr[local];    // SMEM broadcast
    const float2 wv = s_w[local];
    const float wx = wv.x, wy = wv.y;

    const float4* __restrict__ tl = (const float4*)a.x;
    const float4* __restrict__ tr = (const float4*)a.y;
    const float4* __restrict__ bl = (const float4*)a.z;
    const float4* __restrict__ br = (const float4*)a.w;
    float4* __restrict__ o = (float4*)(out + (size_t)item * CCH);

#pragma unroll
    for (int j = 0; j < 4; j++) {
        const int c = lane + j * LANES;
        const float4 vtl = tl[c];
        const float4 vtr = tr[c];
        const float4 vbl = bl[c];
        const float4 vbr = br[c];
        float4 r;
        float t, bt;
        t  = vtl.x + (vtr.x - vtl.x) * wx;  bt = vbl.x + (vbr.x - vbl.x) * wx;  r.x = t + (bt - t) * wy;
        t  = vtl.y + (vtr.y - vtl.y) * wx;  bt = vbl.y + (vbr.y - vbl.y) * wx;  r.y = t + (bt - t) * wy;
        t  = vtl.z + (vtr.z - vtl.z) * wx;  bt = vbl.z + (vbr.z - vbl.z) * wx;  r.z = t + (bt - t) * wy;
        t  = vtl.w + (vtr.w - vtl.w) * wx;  bt = vbl.w + (vbr.w - vbl.w) * wx;  r.w = t + (bt - t) * wy;
        __stcs(&o[c], r);
    }
}

extern "C" void kernel_launch(void* const* d_in, const int* in_sizes, int n_in,
                              void* d_out, int out_size)
{
    const float* boxes = (const float*)d_in[0];
    const float* ishp  = (const float*)d_in[1];
    const float* P2    = (const float*)d_in[2];
    const float* P3    = (const float*)d_in[3];
    const float* P4    = (const float*)d_in[4];
    const float* P5    = (const float*)d_in[5];
    float* out = (float*)d_out;

    // Maximize L1D: kernel uses only ~352B SMEM; prefer minimal SMEM carveout.
    // Deterministic, allocation-free; harmless if the driver ignores it.
    static int carveout_set = 0;
    if (!carveout_set) {
        cudaFuncSetAttribute(roi_fused_kernel,
                             cudaFuncAttributePreferredSharedMemoryCarveout,
                             cudaSharedmemCarveoutMaxL1);
        carveout_set = 1;
    }

    const int B = in_sizes[2] / (256 * 256 * 256);
    const int total_boxes = in_sizes[0] / 4;
    const int boxes_per_batch = total_boxes / B;
    const int total_items = total_boxes * NPTS;

    const int blocks = (total_items + ITEMS_PER_CTA - 1) / ITEMS_PER_CTA;
    roi_fused_kernel<<<blocks, CTA_THREADS>>>(boxes, ishp, P2, P3, P4, P5, out,
                                              total_items, boxes_per_batch);
}

// round 14
// speedup vs baseline: 1.7252x; 1.7252x over previous
#include <cuda_runtime.h>

// PyramidROIAlign: B=2, N=1000 boxes, C=256, 7x7 pool. Single fused kernel.
// R12 champion structure at 64-thread granularity: CTA = 4 items.
// Threads 0..3 compute per-item params into SMEM; barrier (couples only 2
// warps); all threads run the proven gather body (16 lanes/item, unroll-4
// epochs). launch_bounds pins regs<=32 (2048 thr/SM); __stcs write stream.

#define POOL 7
#define NPTS (POOL * POOL)
#define CCH 256
#define LANES 16
#define ITEMS_PER_CTA 4
#define CTA_THREADS 64

__global__ void __launch_bounds__(CTA_THREADS, 32)
roi_fused_kernel(const float* __restrict__ boxes,
                 const float* __restrict__ image_shape,
                 const float* __restrict__ P2,
                 const float* __restrict__ P3,
                 const float* __restrict__ P4,
                 const float* __restrict__ P5,
                 float* __restrict__ out,
                 int total_items, int boxes_per_batch)
{
    __shared__ ulonglong4 s_addr[ITEMS_PER_CTA];
    __shared__ float2     s_w[ITEMS_PER_CTA];

    const int item_base = blockIdx.x * ITEMS_PER_CTA;
    const int tid = threadIdx.x;

    if (tid < ITEMS_PER_CTA) {
        const int item = item_base + tid;
        if (item < total_items) {
            const int bn = item / NPTS;
            const int pt = item - bn * NPTS;
            const int py = pt / POOL;
            const int px = pt - py * POOL;
            const int b  = bn / boxes_per_batch;

            const float4 bx = ((const float4*)boxes)[bn];
            const float y1 = bx.x, x1 = bx.y, y2 = bx.z, x2 = bx.w;
            const float h = y2 - y1;
            const float w = x2 - x1;

            // Level selection — exact reference fp32 op order; rintf == jnp.round.
            const float area = image_shape[0] * image_shape[1];
            float lvlf = log2f(sqrtf(h * w) / (224.0f / sqrtf(area)));
            lvlf = fminf(5.0f, fmaxf(2.0f, 4.0f + rintf(lvlf)));
            const int lvl = (int)lvlf;

            const float* fmap;
            int H;
            if (lvl == 2)      { fmap = P2; H = 256; }
            else if (lvl == 3) { fmap = P3; H = 128; }
            else if (lvl == 4) { fmap = P4; H = 64;  }
            else               { fmap = P5; H = 32;  }
            const int W = H;

            // Reference order: in_y = (y1 + h*gy) * (H-1)
            const float gy = (float)py * (1.0f / 6.0f);
            const float gx = (float)px * (1.0f / 6.0f);
            const float in_y = (y1 + h * gy) * (float)(H - 1);
            const float in_x = (x1 + w * gx) * (float)(W - 1);

            const float y0f = floorf(in_y);
            const float x0f = floorf(in_x);
            const float wy = in_y - y0f;
            const float wx = in_x - x0f;

            int y0  = min(max((int)y0f, 0), H - 1);
            int y1i = min(y0 + 1, H - 1);
            int x0  = min(max((int)x0f, 0), W - 1);
            int x1i = min(x0 + 1, W - 1);

            const unsigned long long base =
                (unsigned long long)fmap + (unsigned long long)b * H * W * CCH * 4ull;
            const unsigned long long rowT = base + (unsigned long long)(y0  * W) * (CCH * 4ull);
            const unsigned long long rowB = base + (unsigned long long)(y1i * W) * (CCH * 4ull);

            ulonglong4 a;
            a.x = rowT + (unsigned long long)x0  * (CCH * 4ull);
            a.y = rowT + (unsigned long long)x1i * (CCH * 4ull);
            a.z = rowB + (unsigned long long)x0  * (CCH * 4ull);
            a.w = rowB + (unsigned long long)x1i * (CCH * 4ull);
            s_addr[tid] = a;
            s_w[tid] = make_float2(wx, wy);
        }
    }
    __syncthreads();

    const int local = tid >> 4;            // item within CTA (0..3)
    const int lane  = tid & (LANES - 1);   // float4 lane group
    const int item = item_base + local;
    if (item >= total_items) return;

    const ulonglong4 a = s_addr[local];    // SMEM broadcast
    const float2 wv = s_w[local];
    const float wx = wv.x, wy = wv.y;

    const float4* __restrict__ tl = (const float4*)a.x;
    const float4* __restrict__ tr = (const float4*)a.y;
    const float4* __restrict__ bl = (const float4*)a.z;
    const float4* __restrict__ br = (const float4*)a.w;
    float4* __restrict__ o = (float4*)(out + (size_t)item * CCH);

#pragma unroll
    for (int j = 0; j < 4; j++) {
        const int c = lane + j * LANES;
        const float4 vtl = tl[c];
        const float4 vtr = tr[c];
        const float4 vbl = bl[c];
        const float4 vbr = br[c];
        float4 r;
        float t, bt;
        t  = vtl.x + (vtr.x - vtl.x) * wx;  bt = vbl.x + (vbr.x - vbl.x) * wx;  r.x = t + (bt - t) * wy;
        t  = vtl.y + (vtr.y - vtl.y) * wx;  bt = vbl.y + (vbr.y - vbl.y) * wx;  r.y = t + (bt - t) * wy;
        t  = vtl.z + (vtr.z - vtl.z) * wx;  bt = vbl.z + (vbr.z - vbl.z) * wx;  r.z = t + (bt - t) * wy;
        t  = vtl.w + (vtr.w - vtl.w) * wx;  bt = vbl.w + (vbr.w - vbl.w) * wx;  r.w = t + (bt - t) * wy;
        __stcs(&o[c], r);
    }
}

extern "C" void kernel_launch(void* const* d_in, const int* in_sizes, int n_in,
                              void* d_out, int out_size)
{
    const float* boxes = (const float*)d_in[0];
    const float* ishp  = (const float*)d_in[1];
    const float* P2    = (const float*)d_in[2];
    const float* P3    = (const float*)d_in[3];
    const float* P4    = (const float*)d_in[4];
    const float* P5    = (const float*)d_in[5];
    float* out = (float*)d_out;

    const int B = in_sizes[2] / (256 * 256 * 256);
    const int total_boxes = in_sizes[0] / 4;
    const int boxes_per_batch = total_boxes / B;
    const int total_items = total_boxes * NPTS;

    const int blocks = (total_items + ITEMS_PER_CTA - 1) / ITEMS_PER_CTA;
    roi_fused_kernel<<<blocks, CTA_THREADS>>>(boxes, ishp, P2, P3, P4, P5, out,
                                              total_items, boxes_per_batch);
}